// round 14
// baseline (speedup 1.0000x reference)
#include <cuda_runtime.h>

#define BATCH 4
#define H 1024
#define W 1024
#define IMG (H * W)
#define NPIX (BATCH * IMG)
#define TW 64
#define TH 64
#define NTX (W / TW)
#define NTY (H / TH)
#define NTILES (BATCH * NTX * NTY)
#define MAXROOTS 1024

// ---------------- scratch ----------------
__device__ unsigned short g_pack[NPIX];   // bits[12:14)=state, bits[0:12)=local root idx
__device__ unsigned int   g_parent[NPIX]; // valid ONLY at local-root positions
__device__ unsigned char  g_flag[NPIX];   // at global-root positions
__device__ unsigned char  g_flagL[NPIX];  // at local-root positions: resolved flag
__device__ unsigned short g_roots[NTILES * MAXROOTS];
__device__ unsigned int   g_cnt[NTILES];

// nibble LUTs: (offset+1) per direction d (kornia order), d0 lowest nibble
#define DXP 0x21000122u
#define DYP 0x00012221u

#define GW0 0.40261994f
#define GW1 0.24420134f
#define GW2 0.05448868f
#define TAN22 0.41421356237309503f
#define TAN67 2.4142135623730951f

__device__ __forceinline__ int reflect_idx(int i, int n) {
    if (i < 0) return -i;
    if (i >= n) return 2 * n - 2 - i;
    return i;
}

// ---- shared-memory union-find ----
__device__ __forceinline__ unsigned lfind(unsigned* p, unsigned i) {
    volatile unsigned* vp = (volatile unsigned*)p;
    unsigned q = vp[i];
    while (q != i) {
        unsigned qq = vp[q];
        if (qq != q) vp[i] = qq;
        i = q; q = qq;
    }
    return i;
}
__device__ __forceinline__ void lunion(unsigned* p, unsigned a, unsigned b) {
    while (true) {
        a = lfind(p, a);
        b = lfind(p, b);
        if (a == b) return;
        unsigned lo = min(a, b), hi = max(a, b);
        unsigned old = atomicCAS(&p[hi], hi, lo);
        if (old == hi) return;
        a = lo; b = old;
    }
}

// ---- global union-find (root positions only) ----
__device__ __forceinline__ unsigned gfind(unsigned i) {
    unsigned p = __ldcg(&g_parent[i]);
    while (p != i) {
        unsigned gp = __ldcg(&g_parent[p]);
        if (gp != p) __stcg(&g_parent[i], gp);
        i = p; p = gp;
    }
    return i;
}
__device__ __forceinline__ void gunion(unsigned a, unsigned b) {
    while (true) {
        a = gfind(a);
        b = gfind(b);
        if (a == b) return;
        unsigned lo = min(a, b), hi = max(a, b);
        unsigned old = atomicCAS(&g_parent[hi], hi, lo);
        if (old == hi) return;
        a = lo; b = old;
    }
}

__device__ __forceinline__ unsigned rootPos(unsigned j, unsigned pk) {
    unsigned l = pk & 4095u;
    unsigned b = j >> 20;
    unsigned y = (j >> 10) & 1023u;
    unsigned x = j & 1023u;
    return (b << 20) + (((y & ~63u) + (l >> 6)) << 10) + (x & ~63u) + (l & 63u);
}

// ================= fused stencil + NMS + threshold + local CCL =================
#define OFF_H 20736
#define OFF_D 40320
#define SMEM_BYTES 44680

__global__ __launch_bounds__(1024, 2) void k_fused(const float* __restrict__ x,
                                                   float* __restrict__ magOut) {
    __shared__ __align__(16) unsigned char sbuf[SMEM_BYTES];
    __shared__ unsigned scnt;

    float (*sG)[72] = (float(*)[72])(sbuf);
    float (*sV)[68] = (float(*)[68])(sbuf);             // aliases sG
    float (*sH)[68] = (float(*)[68])(sbuf + OFF_H);
    float (*sM)[66] = (float(*)[66])(sbuf + OFF_H);     // aliases sH
    unsigned char (*sD)[66] = (unsigned char(*)[66])(sbuf + OFF_D);
    unsigned*      lp    = (unsigned*)(sbuf);           // aliases sV (post-sync)
    unsigned char* ls    = sbuf + 16384;
    unsigned char* sflag = sbuf + OFF_H;                // aliases sM (post-sync)

    const int tileX = blockIdx.x * TW;
    const int tileY = blockIdx.y * TH;
    const int b     = blockIdx.z;
    const int tid   = threadIdx.y * 32 + threadIdx.x;
    const unsigned tileId = ((unsigned)b * NTY + blockIdx.y) * NTX + blockIdx.x;
    const float* base = x + (size_t)b * 3 * IMG;
    const bool interior = (tileX >= 4) && (tileX + TW + 4 <= W) &&
                          (tileY >= 4) && (tileY + TH + 4 <= H);

    if (tid == 0) scnt = 0;

    // gray: 72 x 72
    if (interior) {
        for (int idx = tid; idx < 72 * 72; idx += 1024) {
            int r = idx / 72, c = idx % 72;
            int o = (tileY - 4 + r) * W + (tileX - 4 + c);
            sG[r][c] = 0.299f * base[o] + 0.587f * base[IMG + o] + 0.114f * base[2 * IMG + o];
        }
    } else {
        for (int idx = tid; idx < 72 * 72; idx += 1024) {
            int r = idx / 72, c = idx % 72;
            int yy = reflect_idx(tileY - 4 + r, H);
            int xx = reflect_idx(tileX - 4 + c, W);
            int o = yy * W + xx;
            sG[r][c] = 0.299f * base[o] + 0.587f * base[IMG + o] + 0.114f * base[2 * IMG + o];
        }
    }
    __syncthreads();

    // blurH: 72 rows x 68 cols
    {
        const float w[5] = { GW2, GW1, GW0, GW1, GW2 };
        if (interior) {
            for (int idx = tid; idx < 72 * 68; idx += 1024) {
                int r = idx / 68, c = idx % 68;
                float s = 0.f;
#pragma unroll
                for (int k = 0; k < 5; k++) s += w[k] * sG[r][c + k];
                sH[r][c] = s;
            }
        } else {
            for (int idx = tid; idx < 72 * 68; idx += 1024) {
                int r = idx / 68, c = idx % 68;
                int gx = tileX - 2 + c;
                float s = 0.f;
#pragma unroll
                for (int k = 0; k < 5; k++) {
                    int lx = reflect_idx(gx + k - 2, W) - (tileX - 4);
                    s += w[k] * sG[r][lx];
                }
                sH[r][c] = s;
            }
        }
    }
    __syncthreads();   // sG dead -> sV writable

    // blurV: 68 rows x 68 cols
    {
        const float w[5] = { GW2, GW1, GW0, GW1, GW2 };
        if (interior) {
            for (int idx = tid; idx < 68 * 68; idx += 1024) {
                int r = idx / 68, c = idx % 68;
                float s = 0.f;
#pragma unroll
                for (int k = 0; k < 5; k++) s += w[k] * sH[r + k][c];
                sV[r][c] = s;
            }
        } else {
            for (int idx = tid; idx < 68 * 68; idx += 1024) {
                int r = idx / 68, c = idx % 68;
                int gy = tileY - 2 + r;
                float s = 0.f;
#pragma unroll
                for (int k = 0; k < 5; k++) {
                    int ly = reflect_idx(gy + k - 2, H) - (tileY - 4);
                    s += w[k] * sH[ly][c];
                }
                sV[r][c] = s;
            }
        }
    }
    __syncthreads();   // sH dead -> sM writable

    // sobel: 66 x 66
    for (int idx = tid; idx < 66 * 66; idx += 1024) {
        int r = idx / 66, c = idx % 66;
        float a00, a01, a02, a10, a12, a20, a21, a22;
        if (interior) {
            a00 = sV[r][c];     a01 = sV[r][c + 1];     a02 = sV[r][c + 2];
            a10 = sV[r + 1][c];                         a12 = sV[r + 1][c + 2];
            a20 = sV[r + 2][c]; a21 = sV[r + 2][c + 1]; a22 = sV[r + 2][c + 2];
        } else {
            int gy = tileY - 1 + r;
            int gx = tileX - 1 + c;
            int xm = max(gx - 1, 0), xp = min(gx + 1, W - 1);
            int ym = max(gy - 1, 0), yp = min(gy + 1, H - 1);
            int xc = min(max(gx, 0), W - 1), yc = min(max(gy, 0), H - 1);
            int lxm = xm - (tileX - 2), lxp = xp - (tileX - 2), lxc = xc - (tileX - 2);
            int lym = ym - (tileY - 2), lyp = yp - (tileY - 2), lyc = yc - (tileY - 2);
            a00 = sV[lym][lxm]; a01 = sV[lym][lxc]; a02 = sV[lym][lxp];
            a10 = sV[lyc][lxm];                     a12 = sV[lyc][lxp];
            a20 = sV[lyp][lxm]; a21 = sV[lyp][lxc]; a22 = sV[lyp][lxp];
        }

        float gxv = (a02 - a00) + 2.f * (a12 - a10) + (a22 - a20);
        float gyv = (a20 - a00) + 2.f * (a21 - a01) + (a22 - a02);

        float mag = sqrtf(gxv * gxv + gyv * gyv + 1e-6f);

        float ax = fabsf(gxv), ay = fabsf(gyv);
        int d;
        if (ay <= TAN22 * ax)      d = (gxv >= 0.f) ? 0 : 4;
        else if (ay >= TAN67 * ax) d = (gyv >= 0.f) ? 2 : 6;
        else {
            if (gxv > 0.f) d = (gyv > 0.f) ? 1 : 7;
            else           d = (gyv > 0.f) ? 3 : 5;
        }
        sM[r][c] = mag;
        sD[r][c] = (unsigned char)d;
    }
    __syncthreads();

    // NMS + threshold, 4 pixels/thread (register nibble-LUT offsets)
    unsigned char stv[4];
#pragma unroll
    for (int k = 0; k < 4; k++) {
        int p   = tid + 1024 * k;
        int ly2 = p >> 6, lx2 = p & 63;
        int gx  = tileX + lx2, gy = tileY + ly2;
        float m = sM[ly2 + 1][lx2 + 1];
        int d   = sD[ly2 + 1][lx2 + 1];
        int dn  = (d + 4) & 7;

        int dx1 = (int)((DXP >> (d  * 4)) & 15u) - 1;
        int dy1 = (int)((DYP >> (d  * 4)) & 15u) - 1;
        int dx2 = (int)((DXP >> (dn * 4)) & 15u) - 1;
        int dy2 = (int)((DYP >> (dn * 4)) & 15u) - 1;

        float n1, n2;
        if (interior) {
            n1 = sM[ly2 + 1 + dy1][lx2 + 1 + dx1];
            n2 = sM[ly2 + 1 + dy2][lx2 + 1 + dx2];
        } else {
            int y1 = gy + dy1, x1 = gx + dx1;
            int y2 = gy + dy2, x2 = gx + dx2;
            n1 = (y1 >= 0 && y1 < H && x1 >= 0 && x1 < W)
                 ? sM[ly2 + 1 + dy1][lx2 + 1 + dx1] : 0.f;
            n2 = (y2 >= 0 && y2 < H && x2 >= 0 && x2 < W)
                 ? sM[ly2 + 1 + dy2][lx2 + 1 + dx2] : 0.f;
        }

        bool keep = (m > n1) && (m > n2);
        float mo = keep ? m : 0.f;
        magOut[(b << 20) + (gy << 10) + gx] = mo;
        stv[k] = mo > 0.2f ? 2 : (mo > 0.1f ? 1 : 0);
    }
    __syncthreads();   // sM/sD dead -> lp/ls/sflag writable

    // local CCL init
#pragma unroll
    for (int k = 0; k < 4; k++) {
        int p = tid + 1024 * k;
        ls[p] = stv[k];
        lp[p] = p;
        sflag[p] = 0;
    }
    __syncthreads();

    // reduced unions
#pragma unroll
    for (int k = 0; k < 4; k++) {
        int p = tid + 1024 * k;
        if (stv[k]) {
            int ly2 = p >> 6, lx2 = p & 63;
            bool up = (ly2 > 0) && ls[p - 64];
            bool ul = (ly2 > 0) && (lx2 > 0)  && ls[p - 65];
            bool ur = (ly2 > 0) && (lx2 < 63) && ls[p - 63];
            bool lf = (lx2 > 0) && ls[p - 1];
            if (up) lunion(lp, p, p - 64);
            else {
                if (ul) lunion(lp, p, p - 65);
                if (ur) lunion(lp, p, p - 63);
            }
            if (lf && !(up && ul)) lunion(lp, p, p - 1);
        }
    }
    __syncthreads();

    unsigned rv[4];
#pragma unroll
    for (int k = 0; k < 4; k++) {
        int p = tid + 1024 * k;
        rv[k] = 0;
        if (stv[k]) {
            rv[k] = lfind(lp, p);
            if (stv[k] == 2) sflag[rv[k]] = 1;   // only 1s written
        }
    }
    __syncthreads();

#pragma unroll
    for (int k = 0; k < 4; k++) {
        int p = tid + 1024 * k;
        int ly2 = p >> 6, lx2 = p & 63;
        unsigned gid = (b << 20) + ((tileY + ly2) << 10) + tileX + lx2;
        g_pack[gid] = stv[k] ? (unsigned short)(((unsigned)stv[k] << 12) | rv[k]) : 0;
        if (stv[k] && rv[k] == (unsigned)p) {
            g_parent[gid] = gid;
            g_flag[gid]   = sflag[p];
            unsigned slot = atomicAdd(&scnt, 1u);
            if (slot < MAXROOTS) g_roots[tileId * MAXROOTS + slot] = (unsigned short)p;
        }
    }
    __syncthreads();
    if (tid == 0) g_cnt[tileId] = min(scnt, (unsigned)MAXROOTS);
}

// ====== cross-tile border unions: ILP-4, shared neighbor loads ======
// vertical: 15 seams * 256 y-groups per image; horizontal symmetric.
#define SEAM_T_PER 3840u           // 15 * 256
#define SEAM_T_TOT 15360u          // * BATCH

__global__ void k_merge_border() {
    unsigned id = blockIdx.x * blockDim.x + threadIdx.x;
    bool vert = id < SEAM_T_TOT;
    unsigned t = vert ? id : id - SEAM_T_TOT;
    unsigned b = t / SEAM_T_PER;
    unsigned r = t % SEAM_T_PER;
    unsigned seam = r >> 8, g = r & 255u;

    if (vert) {
        unsigned x  = (seam + 1) << 6;
        unsigned y0 = g << 2;
        unsigned ibase = b * IMG + y0 * W + x;

        unsigned short pki[4];
#pragma unroll
        for (int k = 0; k < 4; k++) pki[k] = g_pack[ibase + k * W];
        unsigned short pup = (y0 > 0) ? g_pack[ibase - W] : (unsigned short)0;
        unsigned short lcol[6];
#pragma unroll
        for (int j = 0; j < 6; j++) {
            int yy = (int)y0 - 1 + j;
            lcol[j] = (yy >= 0 && yy < H)
                      ? g_pack[b * IMG + (unsigned)yy * W + x - 1] : (unsigned short)0;
        }
#pragma unroll
        for (int k = 0; k < 4; k++) {
            unsigned pk = pki[k];
            if (!(pk >> 12)) continue;
            unsigned i  = ibase + k * W;
            unsigned ri = rootPos(i, pk);
            bool bP  = (((k == 0) ? pup : pki[k - 1]) >> 12) != 0;
            unsigned pkL = lcol[k + 1], pkUL = lcol[k], pkDL = lcol[k + 2];
            bool bL = (pkL >> 12) != 0, bUL = (pkUL >> 12) != 0, bDL = (pkDL >> 12) != 0;
            if (bL) {
                if (!(bP && bUL)) gunion(ri, rootPos(i - 1, pkL));
            } else {
                if (bUL && !bP) gunion(ri, rootPos(i - W - 1, pkUL));
                if (bDL)        gunion(ri, rootPos(i + W - 1, pkDL));
            }
        }
    } else {
        unsigned y  = (seam + 1) << 6;
        unsigned x0 = g << 2;
        unsigned ibase = b * IMG + y * W + x0;

        ushort4 p4 = *reinterpret_cast<const ushort4*>(&g_pack[ibase]);
        unsigned short pki[4] = { p4.x, p4.y, p4.z, p4.w };
        unsigned short pl = (x0 > 0) ? g_pack[ibase - 1] : (unsigned short)0;
        unsigned short urow[6];
#pragma unroll
        for (int j = 0; j < 6; j++) {
            int xx = (int)x0 - 1 + j;
            urow[j] = (xx >= 0 && xx < W)
                      ? g_pack[ibase - W - 1 + j] : (unsigned short)0;
        }
#pragma unroll
        for (int k = 0; k < 4; k++) {
            unsigned pk = pki[k];
            if (!(pk >> 12)) continue;
            unsigned x  = x0 + k;
            unsigned i  = ibase + k;
            unsigned ri = rootPos(i, pk);
            bool intra = (x & 63u) != 0;
            unsigned pkU = urow[k + 1], pkUL = urow[k], pkUR = urow[k + 2];
            bool bU = (pkU >> 12) != 0, bUL = (pkUL >> 12) != 0, bUR = (pkUR >> 12) != 0;
            bool bL = ((((k == 0) ? pl : pki[k - 1])) >> 12) != 0;
            bool skip = intra && bL && bUL;
            if (bU) {
                if (!skip) gunion(ri, rootPos(i - W, pkU));
            } else {
                if (bUL && !(intra && bL)) gunion(ri, rootPos(i - W - 1, pkUL));
                if (bUR)                   gunion(ri, rootPos(i - W + 1, pkUR));
            }
        }
    }
}

// ====== flatten roots: lock-step 4-way chases (MLP 4 per hop level) ======
__global__ void k_flatten() {
    unsigned tile = blockIdx.x;
    unsigned cnt  = g_cnt[tile];
    unsigned b    = tile >> 8;
    unsigned ty   = (tile >> 4) & 15u;
    unsigned tx   = tile & 15u;
    unsigned base = (b << 20) + ((ty << 6) << 10) + (tx << 6);

    unsigned pos[4]; bool act[4];
#pragma unroll
    for (int j = 0; j < 4; j++) {
        unsigned s = threadIdx.x + 256u * j;
        act[j] = s < cnt;
        pos[j] = 0;
        if (act[j]) {
            unsigned l = g_roots[tile * MAXROOTS + s];
            pos[j] = base + ((l >> 6) << 10) + (l & 63u);
        }
    }
    unsigned cur[4], p[4];
    unsigned char fg[4];
#pragma unroll
    for (int j = 0; j < 4; j++) if (act[j]) {
        cur[j] = pos[j];
        p[j]   = __ldcg(&g_parent[pos[j]]);
        fg[j]  = g_flag[pos[j]];
    }
    bool any = true;
    while (any) {
        unsigned gp[4];
#pragma unroll
        for (int j = 0; j < 4; j++)
            if (act[j] && p[j] != cur[j]) gp[j] = __ldcg(&g_parent[p[j]]);
        any = false;
#pragma unroll
        for (int j = 0; j < 4; j++)
            if (act[j] && p[j] != cur[j]) {
                if (gp[j] != p[j]) __stcg(&g_parent[cur[j]], gp[j]);   // halving (benign race)
                cur[j] = p[j];
                p[j]   = gp[j];
                if (p[j] != cur[j]) any = true;
            }
    }
#pragma unroll
    for (int j = 0; j < 4; j++) if (act[j]) {
        g_parent[pos[j]] = cur[j];
        if (cur[j] != pos[j] && fg[j]) g_flag[cur[j]] = 1;
    }
}

// ====== push resolved flag to local roots: lock-step 4-way (parent frozen) ======
__global__ void k_flatten2() {
    unsigned tile = blockIdx.x;
    unsigned cnt  = g_cnt[tile];
    unsigned b    = tile >> 8;
    unsigned ty   = (tile >> 4) & 15u;
    unsigned tx   = tile & 15u;
    unsigned base = (b << 20) + ((ty << 6) << 10) + (tx << 6);

    unsigned pos[4]; bool act[4];
#pragma unroll
    for (int j = 0; j < 4; j++) {
        unsigned s = threadIdx.x + 256u * j;
        act[j] = s < cnt;
        pos[j] = 0;
        if (act[j]) {
            unsigned l = g_roots[tile * MAXROOTS + s];
            pos[j] = base + ((l >> 6) << 10) + (l & 63u);
        }
    }
    unsigned cur[4], p[4];
#pragma unroll
    for (int j = 0; j < 4; j++) if (act[j]) {
        cur[j] = pos[j];
        p[j]   = __ldcg(&g_parent[pos[j]]);
    }
    bool any = true;
    while (any) {
        unsigned gp[4];
#pragma unroll
        for (int j = 0; j < 4; j++)
            if (act[j] && p[j] != cur[j]) gp[j] = __ldcg(&g_parent[p[j]]);
        any = false;
#pragma unroll
        for (int j = 0; j < 4; j++)
            if (act[j] && p[j] != cur[j]) {
                cur[j] = p[j];
                p[j]   = gp[j];
                if (p[j] != cur[j]) any = true;
            }
    }
    unsigned char fl[4];
#pragma unroll
    for (int j = 0; j < 4; j++) if (act[j]) fl[j] = g_flag[cur[j]];
#pragma unroll
    for (int j = 0; j < 4; j++) if (act[j]) g_flagL[pos[j]] = fl[j];
}

// ========== final: vectorized ushort4 pack load + float4 store ==========
__global__ __launch_bounds__(256) void k_final(float* __restrict__ edgeOut) {
    unsigned t  = blockIdx.x * 256 + threadIdx.x;
    unsigned i4 = t * 4;
    ushort4 pk4 = *reinterpret_cast<const ushort4*>(&g_pack[i4]);
    unsigned b  = i4 >> 20;
    unsigned y  = (i4 >> 10) & 1023u;
    unsigned x0 = i4 & 1023u;
    unsigned tilebase = (b << 20) + ((y & ~63u) << 10) + (x0 & ~63u);

    unsigned short pks[4] = { pk4.x, pk4.y, pk4.z, pk4.w };
    float v[4];
#pragma unroll
    for (int k = 0; k < 4; k++) {
        v[k] = 0.f;
        unsigned pk = pks[k];
        if (pk >> 12) {
            unsigned l = pk & 4095u;
            unsigned pos = tilebase + ((l >> 6) << 10) + (l & 63u);
            v[k] = __ldcg(&g_flagL[pos]) ? 1.f : 0.f;
        }
    }
    float4 out = { v[0], v[1], v[2], v[3] };
    *reinterpret_cast<float4*>(&edgeOut[i4]) = out;
}

// ---------------- launch ----------------
extern "C" void kernel_launch(void* const* d_in, const int* in_sizes, int n_in,
                              void* d_out, int out_size) {
    const float* x = (const float*)d_in[0];
    float* magOut  = (float*)d_out;
    float* edgeOut = magOut + (size_t)NPIX;

    dim3 fblk(32, 32, 1);
    dim3 fgrd(NTX, NTY, BATCH);
    k_fused<<<fgrd, fblk>>>(x, magOut);

    unsigned nthreads = 2u * SEAM_T_TOT;   // 30720
    k_merge_border<<<(nthreads + 255) / 256, 256>>>();

    k_flatten<<<NTILES, 256>>>();
    k_flatten2<<<NTILES, 256>>>();

    k_final<<<NPIX / 1024, 256>>>(edgeOut);
}

// round 15
// speedup vs baseline: 1.0578x; 1.0578x over previous
#include <cuda_runtime.h>

#define BATCH 4
#define H 1024
#define W 1024
#define IMG (H * W)
#define NPIX (BATCH * IMG)
#define TW 64
#define TH 64
#define NTX (W / TW)
#define NTY (H / TH)
#define NTILES (BATCH * NTX * NTY)
#define MAXROOTS 1024

// ---------------- scratch ----------------
__device__ unsigned short g_pack[NPIX];   // bits[12:14)=state, bits[0:12)=local root idx
__device__ unsigned int   g_parent[NPIX]; // valid ONLY at local-root positions
__device__ unsigned char  g_flag[NPIX];   // at global-root positions
__device__ unsigned char  g_flagL[NPIX];  // at local-root positions: resolved flag
__device__ unsigned short g_roots[NTILES * MAXROOTS];
__device__ unsigned int   g_cnt[NTILES];

// nibble LUTs: (offset+1) per direction d (kornia order), d0 lowest nibble
#define DXP 0x21000122u
#define DYP 0x00012221u

#define GW0 0.40261994f
#define GW1 0.24420134f
#define GW2 0.05448868f
#define TAN22 0.41421356237309503f
#define TAN67 2.4142135623730951f

__device__ __forceinline__ int reflect_idx(int i, int n) {
    if (i < 0) return -i;
    if (i >= n) return 2 * n - 2 - i;
    return i;
}

// ---- shared-memory union-find ----
__device__ __forceinline__ unsigned lfind(unsigned* p, unsigned i) {
    volatile unsigned* vp = (volatile unsigned*)p;
    unsigned q = vp[i];
    while (q != i) {
        unsigned qq = vp[q];
        if (qq != q) vp[i] = qq;
        i = q; q = qq;
    }
    return i;
}
__device__ __forceinline__ void lunion(unsigned* p, unsigned a, unsigned b) {
    while (true) {
        a = lfind(p, a);
        b = lfind(p, b);
        if (a == b) return;
        unsigned lo = min(a, b), hi = max(a, b);
        unsigned old = atomicCAS(&p[hi], hi, lo);
        if (old == hi) return;
        a = lo; b = old;
    }
}

// ---- global union-find (root positions only) ----
__device__ __forceinline__ unsigned gfind(unsigned i) {
    unsigned p = __ldcg(&g_parent[i]);
    while (p != i) {
        unsigned gp = __ldcg(&g_parent[p]);
        if (gp != p) __stcg(&g_parent[i], gp);
        i = p; p = gp;
    }
    return i;
}
__device__ __forceinline__ void gunion(unsigned a, unsigned b) {
    while (true) {
        a = gfind(a);
        b = gfind(b);
        if (a == b) return;
        unsigned lo = min(a, b), hi = max(a, b);
        unsigned old = atomicCAS(&g_parent[hi], hi, lo);
        if (old == hi) return;
        a = lo; b = old;
    }
}

__device__ __forceinline__ unsigned rootPos(unsigned j, unsigned pk) {
    unsigned l = pk & 4095u;
    unsigned b = j >> 20;
    unsigned y = (j >> 10) & 1023u;
    unsigned x = j & 1023u;
    return (b << 20) + (((y & ~63u) + (l >> 6)) << 10) + (x & ~63u) + (l & 63u);
}

// ================= fused stencil + NMS + threshold + local CCL =================
#define OFF_H 20736
#define OFF_D 40320
#define SMEM_BYTES 44680

__global__ __launch_bounds__(1024, 2) void k_fused(const float* __restrict__ x,
                                                   float* __restrict__ magOut) {
    __shared__ __align__(16) unsigned char sbuf[SMEM_BYTES];
    __shared__ unsigned scnt;

    float (*sG)[72] = (float(*)[72])(sbuf);
    float (*sV)[68] = (float(*)[68])(sbuf);             // aliases sG
    float (*sH)[68] = (float(*)[68])(sbuf + OFF_H);
    float (*sM)[66] = (float(*)[66])(sbuf + OFF_H);     // aliases sH
    unsigned char (*sD)[66] = (unsigned char(*)[66])(sbuf + OFF_D);
    unsigned*      lp    = (unsigned*)(sbuf);           // aliases sV (post-sync)
    unsigned char* ls    = sbuf + 16384;
    unsigned char* sflag = sbuf + OFF_H;                // aliases sM (post-sync)

    const int tileX = blockIdx.x * TW;
    const int tileY = blockIdx.y * TH;
    const int b     = blockIdx.z;
    const int tid   = threadIdx.y * 32 + threadIdx.x;
    const unsigned tileId = ((unsigned)b * NTY + blockIdx.y) * NTX + blockIdx.x;
    const float* base = x + (size_t)b * 3 * IMG;
    const bool interior = (tileX >= 4) && (tileX + TW + 4 <= W) &&
                          (tileY >= 4) && (tileY + TH + 4 <= H);

    if (tid == 0) scnt = 0;

    // gray: 72 x 72 (interior: float4 vectorized, 18 vec per row)
    if (interior) {
        for (int idx = tid; idx < 72 * 18; idx += 1024) {
            int r = idx / 18, c4 = idx % 18;
            const float* rowp = base + (tileY - 4 + r) * W + (tileX - 4);
            float4 rr = reinterpret_cast<const float4*>(rowp)[c4];
            float4 gg = reinterpret_cast<const float4*>(rowp + IMG)[c4];
            float4 bb = reinterpret_cast<const float4*>(rowp + 2 * IMG)[c4];
            int c = c4 * 4;
            sG[r][c + 0] = 0.299f * rr.x + 0.587f * gg.x + 0.114f * bb.x;
            sG[r][c + 1] = 0.299f * rr.y + 0.587f * gg.y + 0.114f * bb.y;
            sG[r][c + 2] = 0.299f * rr.z + 0.587f * gg.z + 0.114f * bb.z;
            sG[r][c + 3] = 0.299f * rr.w + 0.587f * gg.w + 0.114f * bb.w;
        }
    } else {
        for (int idx = tid; idx < 72 * 72; idx += 1024) {
            int r = idx / 72, c = idx % 72;
            int yy = reflect_idx(tileY - 4 + r, H);
            int xx = reflect_idx(tileX - 4 + c, W);
            int o = yy * W + xx;
            sG[r][c] = 0.299f * base[o] + 0.587f * base[IMG + o] + 0.114f * base[2 * IMG + o];
        }
    }
    __syncthreads();

    // blurH: 72 rows x 68 cols
    {
        const float w[5] = { GW2, GW1, GW0, GW1, GW2 };
        if (interior) {
            for (int idx = tid; idx < 72 * 68; idx += 1024) {
                int r = idx / 68, c = idx % 68;
                float s = 0.f;
#pragma unroll
                for (int k = 0; k < 5; k++) s += w[k] * sG[r][c + k];
                sH[r][c] = s;
            }
        } else {
            for (int idx = tid; idx < 72 * 68; idx += 1024) {
                int r = idx / 68, c = idx % 68;
                int gx = tileX - 2 + c;
                float s = 0.f;
#pragma unroll
                for (int k = 0; k < 5; k++) {
                    int lx = reflect_idx(gx + k - 2, W) - (tileX - 4);
                    s += w[k] * sG[r][lx];
                }
                sH[r][c] = s;
            }
        }
    }
    __syncthreads();   // sG dead -> sV writable

    // blurV: 68 rows x 68 cols
    {
        const float w[5] = { GW2, GW1, GW0, GW1, GW2 };
        if (interior) {
            for (int idx = tid; idx < 68 * 68; idx += 1024) {
                int r = idx / 68, c = idx % 68;
                float s = 0.f;
#pragma unroll
                for (int k = 0; k < 5; k++) s += w[k] * sH[r + k][c];
                sV[r][c] = s;
            }
        } else {
            for (int idx = tid; idx < 68 * 68; idx += 1024) {
                int r = idx / 68, c = idx % 68;
                int gy = tileY - 2 + r;
                float s = 0.f;
#pragma unroll
                for (int k = 0; k < 5; k++) {
                    int ly = reflect_idx(gy + k - 2, H) - (tileY - 4);
                    s += w[k] * sH[ly][c];
                }
                sV[r][c] = s;
            }
        }
    }
    __syncthreads();   // sH dead -> sM writable

    // sobel: 66 x 66
    for (int idx = tid; idx < 66 * 66; idx += 1024) {
        int r = idx / 66, c = idx % 66;
        float a00, a01, a02, a10, a12, a20, a21, a22;
        if (interior) {
            a00 = sV[r][c];     a01 = sV[r][c + 1];     a02 = sV[r][c + 2];
            a10 = sV[r + 1][c];                         a12 = sV[r + 1][c + 2];
            a20 = sV[r + 2][c]; a21 = sV[r + 2][c + 1]; a22 = sV[r + 2][c + 2];
        } else {
            int gy = tileY - 1 + r;
            int gx = tileX - 1 + c;
            int xm = max(gx - 1, 0), xp = min(gx + 1, W - 1);
            int ym = max(gy - 1, 0), yp = min(gy + 1, H - 1);
            int xc = min(max(gx, 0), W - 1), yc = min(max(gy, 0), H - 1);
            int lxm = xm - (tileX - 2), lxp = xp - (tileX - 2), lxc = xc - (tileX - 2);
            int lym = ym - (tileY - 2), lyp = yp - (tileY - 2), lyc = yc - (tileY - 2);
            a00 = sV[lym][lxm]; a01 = sV[lym][lxc]; a02 = sV[lym][lxp];
            a10 = sV[lyc][lxm];                     a12 = sV[lyc][lxp];
            a20 = sV[lyp][lxm]; a21 = sV[lyp][lxc]; a22 = sV[lyp][lxp];
        }

        float gxv = (a02 - a00) + 2.f * (a12 - a10) + (a22 - a20);
        float gyv = (a20 - a00) + 2.f * (a21 - a01) + (a22 - a02);

        float mag = sqrtf(gxv * gxv + gyv * gyv + 1e-6f);

        float ax = fabsf(gxv), ay = fabsf(gyv);
        int d;
        if (ay <= TAN22 * ax)      d = (gxv >= 0.f) ? 0 : 4;
        else if (ay >= TAN67 * ax) d = (gyv >= 0.f) ? 2 : 6;
        else {
            if (gxv > 0.f) d = (gyv > 0.f) ? 1 : 7;
            else           d = (gyv > 0.f) ? 3 : 5;
        }
        sM[r][c] = mag;
        sD[r][c] = (unsigned char)d;
    }
    __syncthreads();

    // NMS + threshold, 4 pixels/thread (register nibble-LUT offsets)
    unsigned char stv[4];
#pragma unroll
    for (int k = 0; k < 4; k++) {
        int p   = tid + 1024 * k;
        int ly2 = p >> 6, lx2 = p & 63;
        int gx  = tileX + lx2, gy = tileY + ly2;
        float m = sM[ly2 + 1][lx2 + 1];
        int d   = sD[ly2 + 1][lx2 + 1];
        int dn  = (d + 4) & 7;

        int dx1 = (int)((DXP >> (d  * 4)) & 15u) - 1;
        int dy1 = (int)((DYP >> (d  * 4)) & 15u) - 1;
        int dx2 = (int)((DXP >> (dn * 4)) & 15u) - 1;
        int dy2 = (int)((DYP >> (dn * 4)) & 15u) - 1;

        float n1, n2;
        if (interior) {
            n1 = sM[ly2 + 1 + dy1][lx2 + 1 + dx1];
            n2 = sM[ly2 + 1 + dy2][lx2 + 1 + dx2];
        } else {
            int y1 = gy + dy1, x1 = gx + dx1;
            int y2 = gy + dy2, x2 = gx + dx2;
            n1 = (y1 >= 0 && y1 < H && x1 >= 0 && x1 < W)
                 ? sM[ly2 + 1 + dy1][lx2 + 1 + dx1] : 0.f;
            n2 = (y2 >= 0 && y2 < H && x2 >= 0 && x2 < W)
                 ? sM[ly2 + 1 + dy2][lx2 + 1 + dx2] : 0.f;
        }

        bool keep = (m > n1) && (m > n2);
        float mo = keep ? m : 0.f;
        magOut[(b << 20) + (gy << 10) + gx] = mo;
        stv[k] = mo > 0.2f ? 2 : (mo > 0.1f ? 1 : 0);
    }
    __syncthreads();   // sM/sD dead -> lp/ls/sflag writable

    // local CCL init
#pragma unroll
    for (int k = 0; k < 4; k++) {
        int p = tid + 1024 * k;
        ls[p] = stv[k];
        lp[p] = p;
        sflag[p] = 0;
    }
    __syncthreads();

    // reduced unions
#pragma unroll
    for (int k = 0; k < 4; k++) {
        int p = tid + 1024 * k;
        if (stv[k]) {
            int ly2 = p >> 6, lx2 = p & 63;
            bool up = (ly2 > 0) && ls[p - 64];
            bool ul = (ly2 > 0) && (lx2 > 0)  && ls[p - 65];
            bool ur = (ly2 > 0) && (lx2 < 63) && ls[p - 63];
            bool lf = (lx2 > 0) && ls[p - 1];
            if (up) lunion(lp, p, p - 64);
            else {
                if (ul) lunion(lp, p, p - 65);
                if (ur) lunion(lp, p, p - 63);
            }
            if (lf && !(up && ul)) lunion(lp, p, p - 1);
        }
    }
    __syncthreads();

    unsigned rv[4];
#pragma unroll
    for (int k = 0; k < 4; k++) {
        int p = tid + 1024 * k;
        rv[k] = 0;
        if (stv[k]) {
            rv[k] = lfind(lp, p);
            if (stv[k] == 2) sflag[rv[k]] = 1;   // only 1s written
        }
    }
    __syncthreads();

#pragma unroll
    for (int k = 0; k < 4; k++) {
        int p = tid + 1024 * k;
        int ly2 = p >> 6, lx2 = p & 63;
        unsigned gid = (b << 20) + ((tileY + ly2) << 10) + tileX + lx2;
        g_pack[gid] = stv[k] ? (unsigned short)(((unsigned)stv[k] << 12) | rv[k]) : 0;
        if (stv[k] && rv[k] == (unsigned)p) {
            g_parent[gid] = gid;
            g_flag[gid]   = sflag[p];
            unsigned slot = atomicAdd(&scnt, 1u);
            if (slot < MAXROOTS) g_roots[tileId * MAXROOTS + slot] = (unsigned short)p;
        }
    }
    __syncthreads();
    if (tid == 0) g_cnt[tileId] = min(scnt, (unsigned)MAXROOTS);
}

// ================= cross-tile border unions (well-founded reduction) ==========
#define V_PER 15360u
#define V_TOT (4u * V_PER)

__global__ void k_merge_border() {
    unsigned id = blockIdx.x * blockDim.x + threadIdx.x;
    bool vert = id < V_TOT;
    unsigned t = vert ? id : id - V_TOT;
    unsigned b = t / V_PER;
    unsigned r = t % V_PER;

    if (vert) {
        unsigned seam = r >> 10;
        unsigned y = r & 1023;
        unsigned x = (seam + 1) << 6;
        unsigned i = b * IMG + y * W + x;
        unsigned pki = g_pack[i];
        if (!(pki >> 12)) return;
        unsigned ri = rootPos(i, pki);

        unsigned pkL = g_pack[i - 1];
        bool bL = (pkL >> 12) != 0;
        bool bP = false, bUL = false;
        unsigned pkUL = 0;
        if (y > 0) {
            bP   = (g_pack[i - W] >> 12) != 0;
            pkUL = g_pack[i - W - 1];
            bUL  = (pkUL >> 12) != 0;
        }
        if (bL) {
            if (!(bP && bUL)) gunion(ri, rootPos(i - 1, pkL));
        } else {
            if (bUL && !bP) gunion(ri, rootPos(i - W - 1, pkUL));
            if (y < H - 1) {
                unsigned pkDL = g_pack[i + W - 1];
                if (pkDL >> 12) gunion(ri, rootPos(i + W - 1, pkDL));
            }
        }
    } else {
        unsigned seam = r >> 10;
        unsigned x = r & 1023;
        unsigned y = (seam + 1) << 6;
        unsigned i = b * IMG + y * W + x;
        unsigned pki = g_pack[i];
        if (!(pki >> 12)) return;
        unsigned ri = rootPos(i, pki);

        unsigned pkU = g_pack[i - W];
        bool bU = (pkU >> 12) != 0;
        bool intra = (x & 63u) != 0;
        unsigned pkUL = 0;
        bool bL = false, bUL = false;
        if (x > 0) {
            bL   = (g_pack[i - 1] >> 12) != 0;
            pkUL = g_pack[i - W - 1];
            bUL  = (pkUL >> 12) != 0;
        }
        bool skip = intra && bL && bUL;
        if (bU) {
            if (!skip) gunion(ri, rootPos(i - W, pkU));
        } else {
            if (bUL && !(intra && bL)) gunion(ri, rootPos(i - W - 1, pkUL));
            if (x < W - 1) {
                unsigned pkUR = g_pack[i - W + 1];
                if (pkUR >> 12) gunion(ri, rootPos(i - W + 1, pkUR));
            }
        }
    }
}

// ================= flatten roots + OR strong flag to global root =================
__global__ void k_flatten() {
    unsigned tile = blockIdx.x;
    unsigned cnt  = g_cnt[tile];
    unsigned b    = tile >> 8;
    unsigned ty   = (tile >> 4) & 15u;
    unsigned tx   = tile & 15u;
    unsigned base = (b << 20) + ((ty << 6) << 10) + (tx << 6);
    for (unsigned s = threadIdx.x; s < cnt; s += blockDim.x) {
        unsigned l = g_roots[tile * MAXROOTS + s];
        unsigned pos = base + ((l >> 6) << 10) + (l & 63u);
        unsigned rt = gfind(pos);
        g_parent[pos] = rt;
        if (rt != pos && g_flag[pos]) g_flag[rt] = 1;
    }
}

// ===== push resolved flag down to local roots (parent frozen => deterministic) =====
__global__ void k_flatten2() {
    unsigned tile = blockIdx.x;
    unsigned cnt  = g_cnt[tile];
    unsigned b    = tile >> 8;
    unsigned ty   = (tile >> 4) & 15u;
    unsigned tx   = tile & 15u;
    unsigned base = (b << 20) + ((ty << 6) << 10) + (tx << 6);
    for (unsigned s = threadIdx.x; s < cnt; s += blockDim.x) {
        unsigned l = g_roots[tile * MAXROOTS + s];
        unsigned pos = base + ((l >> 6) << 10) + (l & 63u);
        unsigned rt = __ldcg(&g_parent[pos]);
        unsigned p  = __ldcg(&g_parent[rt]);
        while (p != rt) { rt = p; p = __ldcg(&g_parent[rt]); }
        g_flagL[pos] = g_flag[rt];
    }
}

// ========== final: vectorized ushort4 pack load + float4 store ==========
__global__ __launch_bounds__(256) void k_final(float* __restrict__ edgeOut) {
    unsigned t  = blockIdx.x * 256 + threadIdx.x;
    unsigned i4 = t * 4;
    ushort4 pk4 = *reinterpret_cast<const ushort4*>(&g_pack[i4]);
    unsigned b  = i4 >> 20;
    unsigned y  = (i4 >> 10) & 1023u;
    unsigned x0 = i4 & 1023u;
    unsigned tilebase = (b << 20) + ((y & ~63u) << 10) + (x0 & ~63u);

    unsigned short pks[4] = { pk4.x, pk4.y, pk4.z, pk4.w };
    float v[4];
#pragma unroll
    for (int k = 0; k < 4; k++) {
        v[k] = 0.f;
        unsigned pk = pks[k];
        if (pk >> 12) {
            unsigned l = pk & 4095u;
            unsigned pos = tilebase + ((l >> 6) << 10) + (l & 63u);
            v[k] = __ldcg(&g_flagL[pos]) ? 1.f : 0.f;
        }
    }
    float4 out = { v[0], v[1], v[2], v[3] };
    *reinterpret_cast<float4*>(&edgeOut[i4]) = out;
}

// ---------------- launch ----------------
extern "C" void kernel_launch(void* const* d_in, const int* in_sizes, int n_in,
                              void* d_out, int out_size) {
    const float* x = (const float*)d_in[0];
    float* magOut  = (float*)d_out;
    float* edgeOut = magOut + (size_t)NPIX;

    dim3 fblk(32, 32, 1);
    dim3 fgrd(NTX, NTY, BATCH);
    k_fused<<<fgrd, fblk>>>(x, magOut);

    unsigned nborder = 2u * V_TOT;
    k_merge_border<<<(nborder + 255) / 256, 256>>>();

    k_flatten<<<NTILES, 256>>>();
    k_flatten2<<<NTILES, 256>>>();

    k_final<<<NPIX / 1024, 256>>>(edgeOut);
}